// round 17
// baseline (speedup 1.0000x reference)
#include <cuda_runtime.h>

// Math collapse: K and V rows are identical across the sequence dim (age is
// broadcast before the K/V projections), so every score row is constant,
// softmax weights are exactly 1/N, and attended[b,n,:] == age[b]@Wv + bv.
// Output = pixel + broadcast(age @ Wv + bv) over n.
//
// R16 = the proven R6 configuration (grid 256 x 512thr, DSUB=96, split-K x4
// preamble, mod-24 stream loop unroll 8 -> HBM 3716 GB/s) plus a minimal
// prologue: the FIRST 6 strided iterations' pixel loads are issued into
// registers BEFORE the vb GEMV, so the read stream overlaps the preamble.
// Unlike R13's spilling prologue: only 6 float4 (24 regs), no index arrays
// (indices recomputed), 64-reg cap respected.

#define B_DIM 8
#define N_DIM 2048
#define D_DIM 768
#define A_DIM 128

#define DCH   8                        // d-chunks of 96 floats
#define NCH   4                        // n-chunks of 512 rows
#define DSUB  96
#define DSUB4 24                       // float4 per d-chunk
#define NROWS 512
#define TPB   512
#define KSPL  4
#define RSTRIDE4 (D_DIM / 4)           // 192 float4 per full row
#define TOTAL4 (NROWS * DSUB4)         // 12288 float4 per block tile
#define PRE   6                        // prologue iterations (24 payload regs)

__global__ __launch_bounds__(TPB, 2)   // 64-reg cap, 2 CTA/SM
void fused_cross_attn_kernel(const float* __restrict__ pixel,
                             const float* __restrict__ age,
                             const float* __restrict__ Wv,
                             const float* __restrict__ bv,
                             float* __restrict__ out) {
    __shared__ __align__(16) float s_age[A_DIM];
    __shared__ __align__(16) float s_part[KSPL * DSUB];
    __shared__ __align__(16) float s_vb[DSUB];

    const int tid = threadIdx.x;
    const int dch = blockIdx.x;        // 0..7
    const int nch = blockIdx.y;        // 0..3
    const int b   = blockIdx.z;        // 0..7
    const int d0  = dch * DSUB;

    if (tid < A_DIM) s_age[tid] = age[b * A_DIM + tid];

    const int n0    = nch * NROWS;
    const int tile4 = (b * N_DIM + n0) * RSTRIDE4 + dch * DSUB4;
    const float4* __restrict__ p4 = reinterpret_cast<const float4*>(pixel) + tile4;
    float4* __restrict__       o4 = reinterpret_cast<float4*>(out) + tile4;

    // ---- prologue: first PRE strided loads in flight before the preamble
    float4 r[PRE];
#pragma unroll
    for (int j = 0; j < PRE; j++) {
        const int i4  = tid + j * TPB;
        const int row = i4 / DSUB4;                // const-div -> mul/shift
        const int c   = i4 - row * DSUB4;
        r[j] = p4[row * RSTRIDE4 + c];
    }
    __syncthreads();                               // s_age ready

    // ---- preamble: vb slice via split-K x4 (384 threads, 32-long dots)
    if (tid < KSPL * DSUB) {
        const int dl = tid % DSUB;                 // coalesced Wv
        const int k  = tid / DSUB;                 // 0..3
        const int dg = d0 + dl;
        float acc = 0.f;
#pragma unroll
        for (int i = 0; i < A_DIM / KSPL; i++) {
            const int a = k * (A_DIM / KSPL) + i;
            acc = fmaf(s_age[a], Wv[a * D_DIM + dg], acc);
        }
        s_part[k * DSUB + dl] = acc;
    }
    __syncthreads();
    if (tid < DSUB) {
        s_vb[tid] = bv[d0 + tid] + ((s_part[tid] + s_part[DSUB + tid]) +
                    (s_part[2 * DSUB + tid] + s_part[3 * DSUB + tid]));
    }
    __syncthreads();

    const float4* __restrict__ v4 = reinterpret_cast<const float4*>(s_vb);

    // ---- epilogue of prologue: add vb, store (first writes of the kernel)
#pragma unroll
    for (int j = 0; j < PRE; j++) {
        const int i4  = tid + j * TPB;
        const int row = i4 / DSUB4;
        const int c   = i4 - row * DSUB4;
        float4 v = v4[c];
        r[j].x += v.x; r[j].y += v.y; r[j].z += v.z; r[j].w += v.w;
        o4[row * RSTRIDE4 + c] = r[j];
    }

    // ---- main stream: remaining 18 strided iterations (R6 loop shape)
#pragma unroll 8
    for (int i4 = tid + PRE * TPB; i4 < TOTAL4; i4 += TPB) {
        const int row = i4 / DSUB4;
        const int c   = i4 - row * DSUB4;
        const int a   = row * RSTRIDE4 + c;
        float4 p = p4[a];
        float4 v = v4[c];                          // conflict-free LDS.128
        p.x += v.x; p.y += v.y; p.z += v.z; p.w += v.w;
        o4[a] = p;
    }
}

extern "C" void kernel_launch(void* const* d_in, const int* in_sizes, int n_in,
                              void* d_out, int out_size) {
    // metadata order: pixel_features, age_features, Wq, bq, Wk, bk, Wv, bv
    const float* pixel = (const float*)d_in[0];
    const float* age   = (const float*)d_in[1];
    const float* Wv    = (const float*)d_in[6];
    const float* bv    = (const float*)d_in[7];
    float* out = (float*)d_out;

    dim3 grid(DCH, NCH, B_DIM);
    fused_cross_attn_kernel<<<grid, TPB>>>(pixel, age, Wv, bv, out);
}